// round 10
// baseline (speedup 1.0000x reference)
#include <cuda_runtime.h>
#include <cuda_fp16.h>
#include <cstdint>

// RankOnePlanes, round 10: full-precision 3-product fp16 split (rel_err
// ~1e-6) at R8-class cost. vs R9: M=64 warp tiles with np8 column-steps
// (one ldmatrix.x4 = full k32 operand; LDSM & b1/W2 loads amortized over
// 4 row-tiles; 4 independent accumulator chains), bias folded into the
// MMA accumulator init, mask-based exact fp16 split (and.b64+sub2), and
// __launch_bounds__(256,2) for ~112 regs of ILP headroom.

#define LTAB 128
#define CL 32
#define HDIM 128
#define TSTRIDE 36   // floats per table row (4 x 32B quarter-blocks + 16B pad)
#define NTHREADS 256
#define WARPS_PER_CTA 8
#define NBLOCKS 304  // 2 per SM
#define ROWPAD 144   // W1 row bytes: [wh 32h | wl 32h] = 128B + 16B pad
#define TILE_M 64

// ---- smem byte offsets ----
#define SM_TAB 0                          // 3*128*36*4 = 55296
#define SM_W1  55296                      // 128 * 144  = 18432
#define SM_B1  73728                      // 64 float2  = 512
#define SM_W2  74240                      // 64 float2  = 512
#define SMEM_BYTES 74752                  // x2 CTAs = 149.5 KB/SM

typedef unsigned long long ull;

__device__ __forceinline__ uint32_t smem_u32(const void* p) {
    uint32_t a;
    asm("{ .reg .u64 t; cvta.to.shared.u64 t, %1; cvt.u32.u64 %0, t; }"
        : "=r"(a) : "l"(p));
    return a;
}
__device__ __forceinline__ void ldsm_x4(uint32_t addr, uint32_t* r) {
    asm volatile("ldmatrix.sync.aligned.m8n8.x4.shared.b16 {%0,%1,%2,%3}, [%4];"
                 : "=r"(r[0]), "=r"(r[1]), "=r"(r[2]), "=r"(r[3]) : "r"(addr));
}
__device__ __forceinline__ void mma_f16(float4& c, const uint32_t* a,
                                        const uint32_t* b) {
    asm volatile(
        "mma.sync.aligned.m16n8k16.row.col.f32.f16.f16.f32 "
        "{%0,%1,%2,%3}, {%4,%5,%6,%7}, {%8,%9}, {%0,%1,%2,%3};"
        : "+f"(c.x), "+f"(c.y), "+f"(c.z), "+f"(c.w)
        : "r"(a[0]), "r"(a[1]), "r"(a[2]), "r"(a[3]), "r"(b[0]), "r"(b[1]));
}
// pack (lo, hi) floats -> f16x2 (lo in low half)
__device__ __forceinline__ uint32_t pkh(float lo, float hi) {
    uint32_t r;
    asm("cvt.rn.f16x2.f32 %0, %1, %2;" : "=r"(r) : "f"(hi), "f"(lo));
    return r;
}
// ---- f32x2 packed helpers ----
__device__ __forceinline__ ull pk2(float lo, float hi) {
    ull r;
    asm("mov.b64 %0, {%1, %2};" : "=l"(r) : "f"(lo), "f"(hi));
    return r;
}
__device__ __forceinline__ void unpk2(float& lo, float& hi, ull v) {
    asm("mov.b64 {%0, %1}, %2;" : "=f"(lo), "=f"(hi) : "l"(v));
}
__device__ __forceinline__ ull mul2(ull a, ull b) {
    ull d;
    asm("mul.rn.f32x2 %0, %1, %2;" : "=l"(d) : "l"(a), "l"(b));
    return d;
}
__device__ __forceinline__ ull add2(ull a, ull b) {
    ull d;
    asm("add.rn.f32x2 %0, %1, %2;" : "=l"(d) : "l"(a), "l"(b));
    return d;
}
__device__ __forceinline__ ull sub2(ull a, ull b) {
    ull d;
    asm("sub.rn.f32x2 %0, %1, %2;" : "=l"(d) : "l"(a), "l"(b));
    return d;
}
__device__ __forceinline__ ull fma2(ull a, ull b, ull c) {
    ull d;
    asm("fma.rn.f32x2 %0, %1, %2, %3;" : "=l"(d) : "l"(a), "l"(b), "l"(c));
    return d;
}
__device__ __forceinline__ ull and64(ull a, ull m) {
    ull d;
    asm("and.b64 %0, %1, %2;" : "=l"(d) : "l"(a), "l"(m));
    return d;
}

__device__ __forceinline__ void sample_setup(float c, int& r0, int& r1,
                                             float& w0, float& w1) {
    float pos = (c + 1.0f) * 63.5f;
    float f0  = floorf(pos);
    float fr  = pos - f0;
    int i0 = (int)f0;
    int i1 = i0 + 1;
    w0 = ((unsigned)i0 < (unsigned)LTAB) ? (1.0f - fr) : 0.0f;
    w1 = ((unsigned)i1 < (unsigned)LTAB) ? fr : 0.0f;
    r0 = min(max(i0, 0), LTAB - 1);
    r1 = min(max(i1, 0), LTAB - 1);
}

// 8 features of one point (this lane's quarter-block channels), f32x2 math.
// Exact split f = fh + fl via mantissa mask (fh has 10 mantissa bits ->
// fp16-exact for normal range); emits fp16 highs h[4] and residuals l[4].
__device__ __forceinline__ void feats8_hl(const float* __restrict__ sT, int qoff,
                                          float cx, float cy, float cz,
                                          uint32_t* __restrict__ hreg,
                                          uint32_t* __restrict__ lreg) {
    int xr0, xr1, yr0, yr1, zr0, zr1;
    float xw0, xw1, yw0, yw1, zw0, zw1;
    sample_setup(cx, xr0, xr1, xw0, xw1);
    sample_setup(cy, yr0, yr1, yw0, yw1);
    sample_setup(cz, zr0, zr1, zw0, zw1);

    const ulonglong2* X0 = reinterpret_cast<const ulonglong2*>(&sT[(0 * LTAB + xr0) * TSTRIDE + qoff]);
    const ulonglong2* X1 = reinterpret_cast<const ulonglong2*>(&sT[(0 * LTAB + xr1) * TSTRIDE + qoff]);
    const ulonglong2* Y0 = reinterpret_cast<const ulonglong2*>(&sT[(1 * LTAB + yr0) * TSTRIDE + qoff]);
    const ulonglong2* Y1 = reinterpret_cast<const ulonglong2*>(&sT[(1 * LTAB + yr1) * TSTRIDE + qoff]);
    const ulonglong2* Z0 = reinterpret_cast<const ulonglong2*>(&sT[(2 * LTAB + zr0) * TSTRIDE + qoff]);
    const ulonglong2* Z1 = reinterpret_cast<const ulonglong2*>(&sT[(2 * LTAB + zr1) * TSTRIDE + qoff]);

    const ull xw0p = pk2(xw0, xw0), xw1p = pk2(xw1, xw1);
    const ull yw0p = pk2(yw0, yw0), yw1p = pk2(yw1, yw1);
    const ull zw0p = pk2(zw0, zw0), zw1p = pk2(zw1, zw1);
    const ull invRp  = 0x4020000040200000ull;  // {2.5f, 2.5f}
    const ull invR2p = 0x40C8000040C80000ull;  // {6.25f, 6.25f}
    const ull hmask  = 0xFFFFE000FFFFE000ull;  // keep 10 mantissa bits

    ulonglong2 x0 = X0[0], x0b = X0[1];
    ulonglong2 x1 = X1[0], x1b = X1[1];
    ulonglong2 y0 = Y0[0], y0b = Y0[1];
    ulonglong2 y1 = Y1[0], y1b = Y1[1];
    ulonglong2 z0 = Z0[0], z0b = Z0[1];
    ulonglong2 z1 = Z1[0], z1b = Z1[1];

    ull xp[4] = {x0.x, x0.y, x0b.x, x0b.y};
    ull xq[4] = {x1.x, x1.y, x1b.x, x1b.y};
    ull yp[4] = {y0.x, y0.y, y0b.x, y0b.y};
    ull yq[4] = {y1.x, y1.y, y1b.x, y1b.y};
    ull zp[4] = {z0.x, z0.y, z0b.x, z0b.y};
    ull zq[4] = {z1.x, z1.y, z1b.x, z1b.y};

#pragma unroll
    for (int pr = 0; pr < 4; pr++) {
        ull xv = fma2(xq[pr], xw1p, mul2(xp[pr], xw0p));
        ull yv = fma2(yq[pr], yw1p, mul2(yp[pr], yw0p));
        ull zv = fma2(zq[pr], zw1p, mul2(zp[pr], zw0p));
        ull e  = add2(xv, yv);
        ull s  = add2(e, zv);
        ull xy = mul2(xv, yv);
        ull p2 = fma2(zv, e, xy);
        ull p3 = mul2(xy, zv);
        ull f  = fma2(p2, invRp, s);
        f = fma2(p3, invR2p, f);
        ull fh = and64(f, hmask);
        ull fl = sub2(f, fh);
        float ha, hb, la, lb;
        unpk2(ha, hb, fh);
        unpk2(la, lb, fl);
        hreg[pr] = pkh(ha, hb);
        lreg[pr] = pkh(la, lb);
    }
}

__global__ __launch_bounds__(NTHREADS, 2)
void rank1_hmma_kernel(const float* __restrict__ coords,
                       const float* __restrict__ lines,
                       const float* __restrict__ W1,
                       const float* __restrict__ b1,
                       const float* __restrict__ W2,
                       const float* __restrict__ b2,
                       float* __restrict__ out, int M) {
    extern __shared__ char smc[];
    const uint32_t sb = smem_u32(smc);
    float* sT = reinterpret_cast<float*>(smc + SM_TAB);
    float2* sB1 = reinterpret_cast<float2*>(smc + SM_B1);
    float2* sW2 = reinterpret_cast<float2*>(smc + SM_W2);

    const int tid  = threadIdx.x;
    const int wid  = tid >> 5;
    const int lane = tid & 31;

    // ---- stage table: per row, 4 quarter-blocks of 8 permuted channels ----
    // block q holds channels {2q,2q+1,2q+8,2q+9,2q+16,2q+17,2q+24,2q+25}
    for (int idx = tid; idx < 3 * LTAB; idx += NTHREADS) {
        const float* src = lines + idx * CL;
        float v[CL];
#pragma unroll
        for (int j = 0; j < 8; j++) {
            float4 t4 = reinterpret_cast<const float4*>(src)[j];
            v[4 * j + 0] = t4.x; v[4 * j + 1] = t4.y;
            v[4 * j + 2] = t4.z; v[4 * j + 3] = t4.w;
        }
        float* dst = sT + idx * TSTRIDE;
#pragma unroll
        for (int q = 0; q < 4; q++) {
            dst[8 * q + 0] = v[2 * q];      dst[8 * q + 1] = v[2 * q + 1];
            dst[8 * q + 2] = v[2 * q + 8];  dst[8 * q + 3] = v[2 * q + 9];
            dst[8 * q + 4] = v[2 * q + 16]; dst[8 * q + 5] = v[2 * q + 17];
            dst[8 * q + 6] = v[2 * q + 24]; dst[8 * q + 7] = v[2 * q + 25];
        }
    }
    // ---- stage split fp16 W1 rows: [wh(32) | wl(32)], channel identity ----
    if (tid < HDIM) {
        char* dst = smc + SM_W1 + tid * ROWPAD;
        const float4* wrow = reinterpret_cast<const float4*>(W1 + tid * CL);
#pragma unroll
        for (int j = 0; j < 8; j += 2) {
            float4 wa = wrow[j], wb = wrow[j + 1];
            uint32_t h0 = pkh(wa.x, wa.y), h1 = pkh(wa.z, wa.w);
            uint32_t h2 = pkh(wb.x, wb.y), h3 = pkh(wb.z, wb.w);
            __half2 q0 = *reinterpret_cast<__half2*>(&h0);
            __half2 q1 = *reinterpret_cast<__half2*>(&h1);
            __half2 q2 = *reinterpret_cast<__half2*>(&h2);
            __half2 q3 = *reinterpret_cast<__half2*>(&h3);
            uint32_t l0 = pkh(wa.x - __low2float(q0), wa.y - __high2float(q0));
            uint32_t l1 = pkh(wa.z - __low2float(q1), wa.w - __high2float(q1));
            uint32_t l2 = pkh(wb.x - __low2float(q2), wb.y - __high2float(q2));
            uint32_t l3 = pkh(wb.z - __low2float(q3), wb.w - __high2float(q3));
            *reinterpret_cast<uint4*>(dst + j * 8)      = make_uint4(h0, h1, h2, h3);
            *reinterpret_cast<uint4*>(dst + 64 + j * 8) = make_uint4(l0, l1, l2, l3);
        }
    }
    // ---- stage b1, W2 as float2 per column pair ----
    if (tid < HDIM / 2) {
        sB1[tid] = make_float2(b1[2 * tid], b1[2 * tid + 1]);
        sW2[tid] = make_float2(W2[2 * tid], W2[2 * tid + 1]);
    }
    __syncthreads();

    const float bias2 = __ldg(b2);
    const uint32_t sbW1 = sb + SM_W1;

    // B ldmatrix: x4 = [wh k0lo, wh k0hi, wh k1lo, wh k1hi] of 8 n-rows;
    // second x4 at +64B gives wl.
    const uint32_t b_addr_base =
        sbW1 + (uint32_t)(lane & 7) * ROWPAD + (uint32_t)(lane >> 3) * 16;

    const int qoff = (lane & 3) * 8;
    const int base = lane >> 2;

    const int warp_gid    = blockIdx.x * WARPS_PER_CTA + wid;
    const int total_warps = NBLOCKS * WARPS_PER_CTA;
    const int tiles       = (M + TILE_M - 1) / TILE_M;

    for (int t = warp_gid; t < tiles; t += total_warps) {
        // ---- build fp16 split A fragments: 8 points per lane ----
        uint32_t afh[4][2][4];   // [row-tile][k16-chunk][frag reg]
        uint32_t afl[4][2][4];
#pragma unroll
        for (int pi = 0; pi < 8; pi++) {
            int p  = t * TILE_M + base + pi * 8;
            int pc = (p < M) ? p : (M - 1);
            float cx = __ldg(&coords[3 * pc + 0]);
            float cy = __ldg(&coords[3 * pc + 1]);
            float cz = __ldg(&coords[3 * pc + 2]);
            uint32_t h[4], l[4];
            feats8_hl(sT, qoff, cx, cy, cz, h, l);

            int rt = pi >> 1;
            int rs = pi & 1;
            afh[rt][0][rs]     = h[0];
            afh[rt][0][2 + rs] = h[1];
            afh[rt][1][rs]     = h[2];
            afh[rt][1][2 + rs] = h[3];
            afl[rt][0][rs]     = l[0];
            afl[rt][0][2 + rs] = l[1];
            afl[rt][1][rs]     = l[2];
            afl[rt][1][2 + rs] = l[3];
        }

        float oacc[8];
#pragma unroll
        for (int i = 0; i < 8; i++) oacc[i] = 0.0f;

#pragma unroll
        for (int np8 = 0; np8 < 16; np8++) {
            uint32_t bwh[4], bwl[4];
            uint32_t nb = b_addr_base + (uint32_t)(np8 * 8) * ROWPAD;
            ldsm_x4(nb,      bwh);
            ldsm_x4(nb + 64, bwl);

            float2 bb = sB1[np8 * 4 + (lane & 3)];
            float2 ww = sW2[np8 * 4 + (lane & 3)];

#pragma unroll
            for (int rt = 0; rt < 4; rt++) {
                float4 c = make_float4(bb.x, bb.y, bb.x, bb.y);  // bias init
                mma_f16(c, afh[rt][0], &bwh[0]);   // fh*wh k0
                mma_f16(c, afh[rt][1], &bwh[2]);   // fh*wh k1
                mma_f16(c, afh[rt][0], &bwl[0]);   // fh*wl k0
                mma_f16(c, afh[rt][1], &bwl[2]);   // fh*wl k1
                mma_f16(c, afl[rt][0], &bwh[0]);   // fl*wh k0
                mma_f16(c, afl[rt][1], &bwh[2]);   // fl*wh k1

                oacc[2 * rt + 0] = fmaf(fmaxf(c.x, 0.f), ww.x, oacc[2 * rt + 0]);
                oacc[2 * rt + 0] = fmaf(fmaxf(c.y, 0.f), ww.y, oacc[2 * rt + 0]);
                oacc[2 * rt + 1] = fmaf(fmaxf(c.z, 0.f), ww.x, oacc[2 * rt + 1]);
                oacc[2 * rt + 1] = fmaf(fmaxf(c.w, 0.f), ww.y, oacc[2 * rt + 1]);
            }
        }

        // ---- reduce over the 4 lanes sharing each row, then store ----
#pragma unroll
        for (int i = 0; i < 8; i++) {
            oacc[i] += __shfl_xor_sync(0xffffffffu, oacc[i], 1);
            oacc[i] += __shfl_xor_sync(0xffffffffu, oacc[i], 2);
        }
        if ((lane & 3) == 0) {
            int pb = t * TILE_M + base;
#pragma unroll
            for (int rt = 0; rt < 4; rt++) {
                int p0 = pb + rt * 16;
                if (p0     < M) out[p0]     = oacc[2 * rt + 0] + bias2;
                if (p0 + 8 < M) out[p0 + 8] = oacc[2 * rt + 1] + bias2;
            }
        }
    }
}

extern "C" void kernel_launch(void* const* d_in, const int* in_sizes, int n_in,
                              void* d_out, int out_size) {
    const float* coords = (const float*)d_in[0];
    const float* lines  = (const float*)d_in[1];
    const float* W1     = (const float*)d_in[2];
    const float* b1     = (const float*)d_in[3];
    const float* W2     = (const float*)d_in[4];
    const float* b2     = (const float*)d_in[5];
    float* out = (float*)d_out;

    int M = in_sizes[0] / 3;

    cudaFuncSetAttribute(rank1_hmma_kernel,
                         cudaFuncAttributeMaxDynamicSharedMemorySize, SMEM_BYTES);

    rank1_hmma_kernel<<<NBLOCKS, NTHREADS, SMEM_BYTES>>>(
        coords, lines, W1, b1, W2, b2, out, M);
}

// round 11
// speedup vs baseline: 1.0268x; 1.0268x over previous
#include <cuda_runtime.h>
#include <cuda_fp16.h>
#include <cstdint>

// RankOnePlanes, round 11: break the phase-sum (R9/R10 both stuck at the
// 3-product tensor floor / 43% because every warp alternates [serial feat
// phase: tensor idle] / [MMA phase: LSU idle]). Single-warp software
// pipeline: M=32 tiles, double-buffered A fragments; coords of tile
// t+stride loaded at loop top, one next-tile feat point computed after
// each of the 4 MMA step-groups. Math identical to R10 (fp16 3-product
// mask split, rel_err ~7e-7). b1/W2 packed per column-pair -> 1 LDS.128
// per step.

#define LTAB 128
#define CL 32
#define HDIM 128
#define TSTRIDE 36   // floats per table row (4 x 32B quarter-blocks + 16B pad)
#define NTHREADS 256
#define WARPS_PER_CTA 8
#define NBLOCKS 304  // 2 per SM
#define ROWPAD 144   // W1 row bytes: [wh 32h | wl 32h] = 128B + 16B pad
#define TILE_M 32

// ---- smem byte offsets ----
#define SM_TAB 0                          // 3*128*36*4 = 55296
#define SM_W1  55296                      // 128 * 144  = 18432
#define SM_BW  73728                      // 64 float4 (b1,b1,W2,W2) = 1024
#define SMEM_BYTES 74752                  // x2 CTAs = 149.5 KB/SM

typedef unsigned long long ull;

__device__ __forceinline__ uint32_t smem_u32(const void* p) {
    uint32_t a;
    asm("{ .reg .u64 t; cvta.to.shared.u64 t, %1; cvt.u32.u64 %0, t; }"
        : "=r"(a) : "l"(p));
    return a;
}
__device__ __forceinline__ void ldsm_x4(uint32_t addr, uint32_t* r) {
    asm volatile("ldmatrix.sync.aligned.m8n8.x4.shared.b16 {%0,%1,%2,%3}, [%4];"
                 : "=r"(r[0]), "=r"(r[1]), "=r"(r[2]), "=r"(r[3]) : "r"(addr));
}
__device__ __forceinline__ void mma_f16(float4& c, const uint32_t* a,
                                        const uint32_t* b) {
    asm volatile(
        "mma.sync.aligned.m16n8k16.row.col.f32.f16.f16.f32 "
        "{%0,%1,%2,%3}, {%4,%5,%6,%7}, {%8,%9}, {%0,%1,%2,%3};"
        : "+f"(c.x), "+f"(c.y), "+f"(c.z), "+f"(c.w)
        : "r"(a[0]), "r"(a[1]), "r"(a[2]), "r"(a[3]), "r"(b[0]), "r"(b[1]));
}
// pack (lo, hi) floats -> f16x2 (lo in low half)
__device__ __forceinline__ uint32_t pkh(float lo, float hi) {
    uint32_t r;
    asm("cvt.rn.f16x2.f32 %0, %1, %2;" : "=r"(r) : "f"(hi), "f"(lo));
    return r;
}
// ---- f32x2 packed helpers ----
__device__ __forceinline__ ull pk2(float lo, float hi) {
    ull r;
    asm("mov.b64 %0, {%1, %2};" : "=l"(r) : "f"(lo), "f"(hi));
    return r;
}
__device__ __forceinline__ void unpk2(float& lo, float& hi, ull v) {
    asm("mov.b64 {%0, %1}, %2;" : "=f"(lo), "=f"(hi) : "l"(v));
}
__device__ __forceinline__ ull mul2(ull a, ull b) {
    ull d;
    asm("mul.rn.f32x2 %0, %1, %2;" : "=l"(d) : "l"(a), "l"(b));
    return d;
}
__device__ __forceinline__ ull add2(ull a, ull b) {
    ull d;
    asm("add.rn.f32x2 %0, %1, %2;" : "=l"(d) : "l"(a), "l"(b));
    return d;
}
__device__ __forceinline__ ull sub2(ull a, ull b) {
    ull d;
    asm("sub.rn.f32x2 %0, %1, %2;" : "=l"(d) : "l"(a), "l"(b));
    return d;
}
__device__ __forceinline__ ull fma2(ull a, ull b, ull c) {
    ull d;
    asm("fma.rn.f32x2 %0, %1, %2, %3;" : "=l"(d) : "l"(a), "l"(b), "l"(c));
    return d;
}
__device__ __forceinline__ ull and64(ull a, ull m) {
    ull d;
    asm("and.b64 %0, %1, %2;" : "=l"(d) : "l"(a), "l"(m));
    return d;
}

__device__ __forceinline__ void sample_setup(float c, int& r0, int& r1,
                                             float& w0, float& w1) {
    float pos = (c + 1.0f) * 63.5f;
    float f0  = floorf(pos);
    float fr  = pos - f0;
    int i0 = (int)f0;
    int i1 = i0 + 1;
    w0 = ((unsigned)i0 < (unsigned)LTAB) ? (1.0f - fr) : 0.0f;
    w1 = ((unsigned)i1 < (unsigned)LTAB) ? fr : 0.0f;
    r0 = min(max(i0, 0), LTAB - 1);
    r1 = min(max(i1, 0), LTAB - 1);
}

// 8 features of one point (this lane's quarter-block channels), f32x2 math.
// Exact split f = fh + fl via mantissa mask; emits fp16 highs h[4] and
// residuals l[4].
__device__ __forceinline__ void feats8_hl(const float* __restrict__ sT, int qoff,
                                          float cx, float cy, float cz,
                                          uint32_t* __restrict__ hreg,
                                          uint32_t* __restrict__ lreg) {
    int xr0, xr1, yr0, yr1, zr0, zr1;
    float xw0, xw1, yw0, yw1, zw0, zw1;
    sample_setup(cx, xr0, xr1, xw0, xw1);
    sample_setup(cy, yr0, yr1, yw0, yw1);
    sample_setup(cz, zr0, zr1, zw0, zw1);

    const ulonglong2* X0 = reinterpret_cast<const ulonglong2*>(&sT[(0 * LTAB + xr0) * TSTRIDE + qoff]);
    const ulonglong2* X1 = reinterpret_cast<const ulonglong2*>(&sT[(0 * LTAB + xr1) * TSTRIDE + qoff]);
    const ulonglong2* Y0 = reinterpret_cast<const ulonglong2*>(&sT[(1 * LTAB + yr0) * TSTRIDE + qoff]);
    const ulonglong2* Y1 = reinterpret_cast<const ulonglong2*>(&sT[(1 * LTAB + yr1) * TSTRIDE + qoff]);
    const ulonglong2* Z0 = reinterpret_cast<const ulonglong2*>(&sT[(2 * LTAB + zr0) * TSTRIDE + qoff]);
    const ulonglong2* Z1 = reinterpret_cast<const ulonglong2*>(&sT[(2 * LTAB + zr1) * TSTRIDE + qoff]);

    const ull xw0p = pk2(xw0, xw0), xw1p = pk2(xw1, xw1);
    const ull yw0p = pk2(yw0, yw0), yw1p = pk2(yw1, yw1);
    const ull zw0p = pk2(zw0, zw0), zw1p = pk2(zw1, zw1);
    const ull invRp  = 0x4020000040200000ull;  // {2.5f, 2.5f}
    const ull invR2p = 0x40C8000040C80000ull;  // {6.25f, 6.25f}
    const ull hmask  = 0xFFFFE000FFFFE000ull;  // keep 10 mantissa bits

    ulonglong2 x0 = X0[0], x0b = X0[1];
    ulonglong2 x1 = X1[0], x1b = X1[1];
    ulonglong2 y0 = Y0[0], y0b = Y0[1];
    ulonglong2 y1 = Y1[0], y1b = Y1[1];
    ulonglong2 z0 = Z0[0], z0b = Z0[1];
    ulonglong2 z1 = Z1[0], z1b = Z1[1];

    ull xp[4] = {x0.x, x0.y, x0b.x, x0b.y};
    ull xq[4] = {x1.x, x1.y, x1b.x, x1b.y};
    ull yp[4] = {y0.x, y0.y, y0b.x, y0b.y};
    ull yq[4] = {y1.x, y1.y, y1b.x, y1b.y};
    ull zp[4] = {z0.x, z0.y, z0b.x, z0b.y};
    ull zq[4] = {z1.x, z1.y, z1b.x, z1b.y};

#pragma unroll
    for (int pr = 0; pr < 4; pr++) {
        ull xv = fma2(xq[pr], xw1p, mul2(xp[pr], xw0p));
        ull yv = fma2(yq[pr], yw1p, mul2(yp[pr], yw0p));
        ull zv = fma2(zq[pr], zw1p, mul2(zp[pr], zw0p));
        ull e  = add2(xv, yv);
        ull s  = add2(e, zv);
        ull xy = mul2(xv, yv);
        ull p2 = fma2(zv, e, xy);
        ull p3 = mul2(xy, zv);
        ull f  = fma2(p2, invRp, s);
        f = fma2(p3, invR2p, f);
        ull fh = and64(f, hmask);
        ull fl = sub2(f, fh);
        float ha, hb, la, lb;
        unpk2(ha, hb, fh);
        unpk2(la, lb, fl);
        hreg[pr] = pkh(ha, hb);
        lreg[pr] = pkh(la, lb);
    }
}

__global__ __launch_bounds__(NTHREADS, 2)
void rank1_hmma_kernel(const float* __restrict__ coords,
                       const float* __restrict__ lines,
                       const float* __restrict__ W1,
                       const float* __restrict__ b1,
                       const float* __restrict__ W2,
                       const float* __restrict__ b2,
                       float* __restrict__ out, int M) {
    extern __shared__ char smc[];
    float* sT = reinterpret_cast<float*>(smc + SM_TAB);
    float4* sBW = reinterpret_cast<float4*>(smc + SM_BW);
    const uint32_t sb = smem_u32(smc);

    const int tid  = threadIdx.x;
    const int wid  = tid >> 5;
    const int lane = tid & 31;

    // ---- stage table: per row, 4 quarter-blocks of 8 permuted channels ----
    for (int idx = tid; idx < 3 * LTAB; idx += NTHREADS) {
        const float* src = lines + idx * CL;
        float v[CL];
#pragma unroll
        for (int j = 0; j < 8; j++) {
            float4 t4 = reinterpret_cast<const float4*>(src)[j];
            v[4 * j + 0] = t4.x; v[4 * j + 1] = t4.y;
            v[4 * j + 2] = t4.z; v[4 * j + 3] = t4.w;
        }
        float* dst = sT + idx * TSTRIDE;
#pragma unroll
        for (int q = 0; q < 4; q++) {
            dst[8 * q + 0] = v[2 * q];      dst[8 * q + 1] = v[2 * q + 1];
            dst[8 * q + 2] = v[2 * q + 8];  dst[8 * q + 3] = v[2 * q + 9];
            dst[8 * q + 4] = v[2 * q + 16]; dst[8 * q + 5] = v[2 * q + 17];
            dst[8 * q + 6] = v[2 * q + 24]; dst[8 * q + 7] = v[2 * q + 25];
        }
    }
    // ---- stage split fp16 W1 rows: [wh(32) | wl(32)] ----
    if (tid < HDIM) {
        char* dst = smc + SM_W1 + tid * ROWPAD;
        const float4* wrow = reinterpret_cast<const float4*>(W1 + tid * CL);
#pragma unroll
        for (int j = 0; j < 8; j += 2) {
            float4 wa = wrow[j], wb = wrow[j + 1];
            uint32_t h0 = pkh(wa.x, wa.y), h1 = pkh(wa.z, wa.w);
            uint32_t h2 = pkh(wb.x, wb.y), h3 = pkh(wb.z, wb.w);
            __half2 q0 = *reinterpret_cast<__half2*>(&h0);
            __half2 q1 = *reinterpret_cast<__half2*>(&h1);
            __half2 q2 = *reinterpret_cast<__half2*>(&h2);
            __half2 q3 = *reinterpret_cast<__half2*>(&h3);
            uint32_t l0 = pkh(wa.x - __low2float(q0), wa.y - __high2float(q0));
            uint32_t l1 = pkh(wa.z - __low2float(q1), wa.w - __high2float(q1));
            uint32_t l2 = pkh(wb.x - __low2float(q2), wb.y - __high2float(q2));
            uint32_t l3 = pkh(wb.z - __low2float(q3), wb.w - __high2float(q3));
            *reinterpret_cast<uint4*>(dst + j * 8)      = make_uint4(h0, h1, h2, h3);
            *reinterpret_cast<uint4*>(dst + 64 + j * 8) = make_uint4(l0, l1, l2, l3);
        }
    }
    // ---- stage packed (b1,b1,W2,W2) per column pair ----
    if (tid < HDIM / 2) {
        sBW[tid] = make_float4(b1[2 * tid], b1[2 * tid + 1],
                               W2[2 * tid], W2[2 * tid + 1]);
    }
    __syncthreads();

    const float bias2 = __ldg(b2);
    const uint32_t b_addr_base =
        (sb + SM_W1) + (uint32_t)(lane & 7) * ROWPAD + (uint32_t)(lane >> 3) * 16;

    const int qoff = (lane & 3) * 8;
    const int base = lane >> 2;

    const int warp_gid    = blockIdx.x * WARPS_PER_CTA + wid;
    const int total_warps = NBLOCKS * WARPS_PER_CTA;
    const int tiles       = (M + TILE_M - 1) / TILE_M;

    uint32_t curh[2][2][4], curl[2][2][4];
    uint32_t nxth[2][2][4], nxtl[2][2][4];
    float cn[12];

    int t = warp_gid;
    if (t < tiles) {
        // ---- prologue: coords + feats for first tile ----
#pragma unroll
        for (int g = 0; g < 4; g++) {
            int p  = t * TILE_M + base + g * 8;
            int pc = (p < M) ? p : (M - 1);
            cn[3 * g + 0] = __ldg(&coords[3 * pc + 0]);
            cn[3 * g + 1] = __ldg(&coords[3 * pc + 1]);
            cn[3 * g + 2] = __ldg(&coords[3 * pc + 2]);
        }
#pragma unroll
        for (int g = 0; g < 4; g++) {
            uint32_t h[4], l[4];
            feats8_hl(sT, qoff, cn[3 * g], cn[3 * g + 1], cn[3 * g + 2], h, l);
            int rt = g >> 1, rs = g & 1;
            curh[rt][0][rs] = h[0]; curh[rt][0][2 + rs] = h[1];
            curh[rt][1][rs] = h[2]; curh[rt][1][2 + rs] = h[3];
            curl[rt][0][rs] = l[0]; curl[rt][0][2 + rs] = l[1];
            curl[rt][1][rs] = l[2]; curl[rt][1][2 + rs] = l[3];
        }

        for (; t < tiles; t += total_warps) {
            const int tn = t + total_warps;
            const bool hasn = tn < tiles;

            // issue next-tile coord loads early (latency hidden by MMAs)
            if (hasn) {
#pragma unroll
                for (int g = 0; g < 4; g++) {
                    int p  = tn * TILE_M + base + g * 8;
                    int pc = (p < M) ? p : (M - 1);
                    cn[3 * g + 0] = __ldg(&coords[3 * pc + 0]);
                    cn[3 * g + 1] = __ldg(&coords[3 * pc + 1]);
                    cn[3 * g + 2] = __ldg(&coords[3 * pc + 2]);
                }
            }

            float oacc[4] = {0.f, 0.f, 0.f, 0.f};

#pragma unroll
            for (int g = 0; g < 4; g++) {
                // ---- 4 np8 MMA steps on current tile ----
#pragma unroll
                for (int s = 0; s < 4; s++) {
                    const int np8 = g * 4 + s;
                    uint32_t bwh[4], bwl[4];
                    uint32_t nb = b_addr_base + (uint32_t)(np8 * 8) * ROWPAD;
                    ldsm_x4(nb,      bwh);
                    ldsm_x4(nb + 64, bwl);
                    float4 bw = sBW[np8 * 4 + (lane & 3)];
#pragma unroll
                    for (int rt = 0; rt < 2; rt++) {
                        float4 c = make_float4(bw.x, bw.y, bw.x, bw.y);
                        mma_f16(c, curh[rt][0], &bwh[0]);   // fh*wh k0
                        mma_f16(c, curh[rt][1], &bwh[2]);   // fh*wh k1
                        mma_f16(c, curh[rt][0], &bwl[0]);   // fh*wl k0
                        mma_f16(c, curh[rt][1], &bwl[2]);   // fh*wl k1
                        mma_f16(c, curl[rt][0], &bwh[0]);   // fl*wh k0
                        mma_f16(c, curl[rt][1], &bwh[2]);   // fl*wh k1
                        oacc[2 * rt + 0] = fmaf(fmaxf(c.x, 0.f), bw.z, oacc[2 * rt + 0]);
                        oacc[2 * rt + 0] = fmaf(fmaxf(c.y, 0.f), bw.w, oacc[2 * rt + 0]);
                        oacc[2 * rt + 1] = fmaf(fmaxf(c.z, 0.f), bw.z, oacc[2 * rt + 1]);
                        oacc[2 * rt + 1] = fmaf(fmaxf(c.w, 0.f), bw.w, oacc[2 * rt + 1]);
                    }
                }
                // ---- one next-tile feat point, overlapped with MMAs ----
                if (hasn) {
                    uint32_t h[4], l[4];
                    feats8_hl(sT, qoff, cn[3 * g], cn[3 * g + 1], cn[3 * g + 2], h, l);
                    int rt = g >> 1, rs = g & 1;
                    nxth[rt][0][rs] = h[0]; nxth[rt][0][2 + rs] = h[1];
                    nxth[rt][1][rs] = h[2]; nxth[rt][1][2 + rs] = h[3];
                    nxtl[rt][0][rs] = l[0]; nxtl[rt][0][2 + rs] = l[1];
                    nxtl[rt][1][rs] = l[2]; nxtl[rt][1][2 + rs] = l[3];
                }
            }

            // ---- reduce + store current tile ----
#pragma unroll
            for (int i = 0; i < 4; i++) {
                oacc[i] += __shfl_xor_sync(0xffffffffu, oacc[i], 1);
                oacc[i] += __shfl_xor_sync(0xffffffffu, oacc[i], 2);
            }
            if ((lane & 3) == 0) {
                int pb = t * TILE_M + base;
                if (pb      < M) out[pb]      = oacc[0] + bias2;
                if (pb + 8  < M) out[pb + 8]  = oacc[1] + bias2;
                if (pb + 16 < M) out[pb + 16] = oacc[2] + bias2;
                if (pb + 24 < M) out[pb + 24] = oacc[3] + bias2;
            }

            // ---- rotate buffers ----
            if (hasn) {
#pragma unroll
                for (int rt = 0; rt < 2; rt++)
#pragma unroll
                    for (int kc = 0; kc < 2; kc++)
#pragma unroll
                        for (int r = 0; r < 4; r++) {
                            curh[rt][kc][r] = nxth[rt][kc][r];
                            curl[rt][kc][r] = nxtl[rt][kc][r];
                        }
            }
        }
    }
}

extern "C" void kernel_launch(void* const* d_in, const int* in_sizes, int n_in,
                              void* d_out, int out_size) {
    const float* coords = (const float*)d_in[0];
    const float* lines  = (const float*)d_in[1];
    const float* W1     = (const float*)d_in[2];
    const float* b1     = (const float*)d_in[3];
    const float* W2     = (const float*)d_in[4];
    const float* b2     = (const float*)d_in[5];
    float* out = (float*)d_out;

    int M = in_sizes[0] / 3;

    cudaFuncSetAttribute(rank1_hmma_kernel,
                         cudaFuncAttributeMaxDynamicSharedMemorySize, SMEM_BYTES);

    rank1_hmma_kernel<<<NBLOCKS, NTHREADS, SMEM_BYTES>>>(
        coords, lines, W1, b1, W2, b2, out, M);
}